// round 4
// baseline (speedup 1.0000x reference)
#include <cuda_runtime.h>
#include <math.h>

// ---------------- problem constants ----------------
#define N_CAM   2
#define PH      96
#define PW      144
#define NPTS    200
#define MIN_D   1.0f
#define MAX_D   4000.0f
#define VD      32
#define VH      128
#define VW      384
#define VOXELSZ 2.5f

#define DHW   (VD*VH*VW)
#define HW    (VH*VW)
#define NRAYS (N_CAM*PH*PW)
#define STEP_D ((MAX_D - MIN_D) / (float)(NPTS - 1))

#define HX (VOXELSZ * (VW - 1) * 0.5f)
#define HY (VOXELSZ * (VH - 1) * 0.5f)
#define HZ (VOXELSZ * (VD - 1) * 0.5f)

#define LPR 8                                    // lanes per ray
#define THREADS    256
#define RAY_BLOCKS ((NRAYS * LPR) / THREADS)     // 864 (exact)
#define BEV_BLOCKS ((HW / 4 + THREADS - 1) / THREADS)  // 48
#define NBLOCKS    (RAY_BLOCKS + BEV_BLOCKS)     // 912

// scratch for deterministic cross-block reduction (overwritten every replay)
__device__ float    g_partial[NBLOCKS][3];
__device__ unsigned g_count = 0;

__device__ __forceinline__ float huber01(float x, float y) {
    float d = x - y;
    float v = fmaf(d * d, 100.0f, 1.0f);
    return (sqrtf(v) - 1.0f) * 0.1f;
}

__global__ void __launch_bounds__(THREADS)
fused_loss_kernel(
    const float* __restrict__ dens,   // (VD,VH,VW)
    const float* __restrict__ cols,   // (3,VD,VH,VW)
    const float* __restrict__ tsil,   // (N_CAM,PH,PW)
    const float* __restrict__ timg,   // (N_CAM,PH,PW,3)
    const float* __restrict__ focal,
    const float* __restrict__ princ,
    const float* __restrict__ Rm,
    const float* __restrict__ Tv,
    float* __restrict__ out)
{
    __shared__ float s_a[THREADS/32], s_b[THREADS/32];
    __shared__ bool  s_last;

    const int tid  = threadIdx.x;
    const int lane = tid & 31;
    const int warp = tid >> 5;

    float p0 = 0.0f, p1 = 0.0f, p2 = 0.0f;   // block partials (color, sil, bev)

    if (blockIdx.x < RAY_BLOCKS) {
        // ---------------- ray blocks: LPR lanes per ray ----------------
        int g   = blockIdx.x * THREADS + tid;    // < NRAYS*LPR exactly
        int idx = g >> 3;                         // ray id
        int sub = g & 7;                          // lane-within-ray

        int w = idx % PW;
        int h = (idx / PW) % PH;
        int n = idx / (PW * PH);

        float fx = focal[n*2+0], fy = focal[n*2+1];
        float px = princ[n*2+0], py = princ[n*2+1];
        float dcx = ((float)w + 0.5f - px) / fx;
        float dcy = ((float)h + 0.5f - py) / fy;

        const float* R = Rm + n*9;
        float Tx = Tv[n*3+0], Ty = Tv[n*3+1], Tz = Tv[n*3+2];

        float dx = dcx*R[0] + dcy*R[1] + R[2];
        float dy = dcx*R[3] + dcy*R[4] + R[5];
        float dz = dcx*R[6] + dcy*R[7] + R[8];
        float ox = -(Tx*R[0] + Ty*R[1] + Tz*R[2]);
        float oy = -(Tx*R[3] + Ty*R[4] + Tz*R[5]);
        float oz = -(Tx*R[6] + Ty*R[7] + Tz*R[8]);

        // slab test in grid space: g = A + B*t, nonzero only for g in (-1, N)
        const float cx = 0.5f * (VW - 1), cy = 0.5f * (VH - 1), cz = 0.5f * (VD - 1);
        float Ax = ox / HX * cx + cx, Bx = dx / HX * cx;
        float Ay = oy / HY * cy + cy, By = dy / HY * cy;
        float Az = oz / HZ * cz + cz, Bz = dz / HZ * cz;

        float tmin = MIN_D, tmax = MAX_D;
        {
            const float lo = -1.001f, hi = (float)VW + 0.001f;
            if (fabsf(Bx) > 1e-20f) {
                float t1 = (lo - Ax) / Bx, t2 = (hi - Ax) / Bx;
                tmin = fmaxf(tmin, fminf(t1, t2)); tmax = fminf(tmax, fmaxf(t1, t2));
            } else if (Ax <= lo || Ax >= hi) { tmax = tmin - 1.0f; }
        }
        {
            const float lo = -1.001f, hi = (float)VH + 0.001f;
            if (fabsf(By) > 1e-20f) {
                float t1 = (lo - Ay) / By, t2 = (hi - Ay) / By;
                tmin = fmaxf(tmin, fminf(t1, t2)); tmax = fminf(tmax, fmaxf(t1, t2));
            } else if (Ay <= lo || Ay >= hi) { tmax = tmin - 1.0f; }
        }
        {
            const float lo = -1.001f, hi = (float)VD + 0.001f;
            if (fabsf(Bz) > 1e-20f) {
                float t1 = (lo - Az) / Bz, t2 = (hi - Az) / Bz;
                tmin = fmaxf(tmin, fminf(t1, t2)); tmax = fminf(tmax, fmaxf(t1, t2));
            } else if (Az <= lo || Az >= hi) { tmax = tmin - 1.0f; }
        }

        int i0 = 0, i1 = -1;
        if (tmax >= tmin) {
            i0 = (int)ceilf ((tmin - MIN_D) / STEP_D - 1e-4f);
            i1 = (int)floorf((tmax - MIN_D) / STEP_D + 1e-4f);
            if (i0 < 0) i0 = 0;
            if (i1 > NPTS - 1) i1 = NPTS - 1;
        }

        // this lane's contiguous chunk of samples
        int nsamp = i1 - i0 + 1;                 // may be <= 0
        int chunk = (nsamp + LPR - 1) >> 3;      // per-lane count (>=0)
        int s0 = i0 + sub * chunk;
        int s1 = s0 + chunk - 1;
        if (s1 > i1) s1 = i1;

        float trans = 1.0f;                      // local prod(1-d)
        float fr = 0.0f, fg = 0.0f, fb = 0.0f;   // local over-composited rgb

        for (int i = s0; i <= s1; ++i) {
            float t = fmaf((float)i, STEP_D, MIN_D);
            float ptx = fmaf(t, dx, ox);
            float pty = fmaf(t, dy, oy);
            float ptz = fmaf(t, dz, oz);
            float gx = (ptx / HX + 1.0f) * (0.5f * (VW - 1));
            float gy = (pty / HY + 1.0f) * (0.5f * (VH - 1));
            float gz = (ptz / HZ + 1.0f) * (0.5f * (VD - 1));

            float x0f = floorf(gx), y0f = floorf(gy), z0f = floorf(gz);
            float frx = gx - x0f, fry = gy - y0f, frz = gz - z0f;
            int ix0 = (int)x0f, iy0 = (int)y0f, iz0 = (int)z0f;

            float wx[2] = {1.0f - frx, frx};
            float wy[2] = {1.0f - fry, fry};
            float wz[2] = {1.0f - frz, frz};
            bool vx[2] = {ix0 >= 0 && ix0 < VW, ix0 + 1 >= 0 && ix0 + 1 < VW};
            bool vy[2] = {iy0 >= 0 && iy0 < VH, iy0 + 1 >= 0 && iy0 + 1 < VH};
            bool vz[2] = {iz0 >= 0 && iz0 < VD, iz0 + 1 >= 0 && iz0 + 1 < VD};

            float ad = 0.0f, ar = 0.0f, ag = 0.0f, ab = 0.0f;
            #pragma unroll
            for (int cdz = 0; cdz < 2; ++cdz) {
                if (!vz[cdz]) continue;
                int zb = (iz0 + cdz) * HW;
                float wzv = wz[cdz];
                #pragma unroll
                for (int cdy = 0; cdy < 2; ++cdy) {
                    if (!vy[cdy]) continue;
                    int yb = zb + (iy0 + cdy) * VW;
                    float wzy = wzv * wy[cdy];
                    #pragma unroll
                    for (int cdx = 0; cdx < 2; ++cdx) {
                        if (!vx[cdx]) continue;
                        int f = yb + ix0 + cdx;
                        float wt = wzy * wx[cdx];
                        ad = fmaf(wt, __ldg(dens + f),         ad);
                        ar = fmaf(wt, __ldg(cols + f),         ar);
                        ag = fmaf(wt, __ldg(cols + f + DHW),   ag);
                        ab = fmaf(wt, __ldg(cols + f + 2*DHW), ab);
                    }
                }
            }

            float wgt = ad * trans;
            fr = fmaf(wgt, ar, fr);
            fg = fmaf(wgt, ag, fg);
            fb = fmaf(wgt, ab, fb);
            trans *= (1.0f - ad);
        }

        // ---- compose the 8 lane-chunks: (F,T) ⊗ (F',T') = (F + T F', T T') ----
        #pragma unroll
        for (int o = 1; o < LPR; o <<= 1) {
            float Tn  = __shfl_down_sync(0xffffffffu, trans, o, LPR);
            float frn = __shfl_down_sync(0xffffffffu, fr,    o, LPR);
            float fgn = __shfl_down_sync(0xffffffffu, fg,    o, LPR);
            float fbn = __shfl_down_sync(0xffffffffu, fb,    o, LPR);
            fr = fmaf(trans, frn, fr);
            fg = fmaf(trans, fgn, fg);
            fb = fmaf(trans, fbn, fb);
            trans *= Tn;
        }

        float csum = 0.0f, ssum = 0.0f;
        if (sub == 0) {
            float opacity = 1.0f - trans;
            ssum = huber01(opacity, tsil[idx]);
            const float* ti = timg + (size_t)idx * 3;
            csum = huber01(fr, ti[0]) + huber01(fg, ti[1]) + huber01(fb, ti[2]);
        }

        // block reduce
        #pragma unroll
        for (int o = 16; o > 0; o >>= 1) {
            csum += __shfl_down_sync(0xffffffffu, csum, o);
            ssum += __shfl_down_sync(0xffffffffu, ssum, o);
        }
        if (lane == 0) { s_a[warp] = csum; s_b[warp] = ssum; }
        __syncthreads();
        if (warp == 0) {
            float a = (lane < THREADS/32) ? s_a[lane] : 0.0f;
            float b = (lane < THREADS/32) ? s_b[lane] : 0.0f;
            #pragma unroll
            for (int o = 4; o > 0; o >>= 1) {
                a += __shfl_down_sync(0xffffffffu, a, o);
                b += __shfl_down_sync(0xffffffffu, b, o);
            }
            if (lane == 0) { p0 = a; p1 = b; }
        }
    } else {
        // ---------------- BEV blocks: mean |max_z dens| ----------------
        int cidx = (blockIdx.x - RAY_BLOCKS) * THREADS + tid;   // float4 column index
        float bsum = 0.0f;
        if (cidx < HW / 4) {
            const float4* d4 = (const float4*)dens;
            float4 m = __ldg(d4 + cidx);
            #pragma unroll
            for (int z = 1; z < VD; ++z) {
                float4 v = __ldg(d4 + cidx + z * (HW / 4));
                m.x = fmaxf(m.x, v.x); m.y = fmaxf(m.y, v.y);
                m.z = fmaxf(m.z, v.z); m.w = fmaxf(m.w, v.w);
            }
            bsum = fabsf(m.x) + fabsf(m.y) + fabsf(m.z) + fabsf(m.w);
        }
        #pragma unroll
        for (int o = 16; o > 0; o >>= 1)
            bsum += __shfl_down_sync(0xffffffffu, bsum, o);
        if (lane == 0) s_a[warp] = bsum;
        __syncthreads();
        if (warp == 0) {
            float a = (lane < THREADS/32) ? s_a[lane] : 0.0f;
            #pragma unroll
            for (int o = 4; o > 0; o >>= 1)
                a += __shfl_down_sync(0xffffffffu, a, o);
            if (lane == 0) p2 = a;
        }
    }

    // ---------------- publish partial, last block reduces ----------------
    if (tid == 0) {
        g_partial[blockIdx.x][0] = p0;
        g_partial[blockIdx.x][1] = p1;
        g_partial[blockIdx.x][2] = p2;
        __threadfence();
        unsigned prev = atomicAdd(&g_count, 1u);
        s_last = (prev == NBLOCKS - 1);
    }
    __syncthreads();

    if (s_last) {
        float a = 0.0f, b = 0.0f, c = 0.0f;
        for (int i = tid; i < NBLOCKS; i += THREADS) {
            a += g_partial[i][0];
            b += g_partial[i][1];
            c += g_partial[i][2];
        }
        #pragma unroll
        for (int o = 16; o > 0; o >>= 1) {
            a += __shfl_down_sync(0xffffffffu, a, o);
            b += __shfl_down_sync(0xffffffffu, b, o);
            c += __shfl_down_sync(0xffffffffu, c, o);
        }
        __shared__ float r_a[THREADS/32], r_b[THREADS/32], r_c[THREADS/32];
        if (lane == 0) { r_a[warp] = a; r_b[warp] = b; r_c[warp] = c; }
        __syncthreads();
        if (warp == 0) {
            a = (lane < THREADS/32) ? r_a[lane] : 0.0f;
            b = (lane < THREADS/32) ? r_b[lane] : 0.0f;
            c = (lane < THREADS/32) ? r_c[lane] : 0.0f;
            #pragma unroll
            for (int o = 4; o > 0; o >>= 1) {
                a += __shfl_down_sync(0xffffffffu, a, o);
                b += __shfl_down_sync(0xffffffffu, b, o);
                c += __shfl_down_sync(0xffffffffu, c, o);
            }
            if (lane == 0) {
                out[0] = a * (1.0f / (float)(NRAYS * 3));
                out[1] = b * (1.0f / (float)NRAYS);
                out[2] = c * (1.0f / (float)HW);
                g_count = 0;   // reset for next graph replay
            }
        }
    }
}

extern "C" void kernel_launch(void* const* d_in, const int* in_sizes, int n_in,
                              void* d_out, int out_size) {
    const float* dens  = (const float*)d_in[0];
    const float* cols  = (const float*)d_in[1];
    const float* tsil  = (const float*)d_in[2];
    const float* timg  = (const float*)d_in[3];
    const float* focal = (const float*)d_in[4];
    const float* princ = (const float*)d_in[5];
    const float* Rm    = (const float*)d_in[6];
    const float* Tv    = (const float*)d_in[7];
    float* out = (float*)d_out;

    fused_loss_kernel<<<NBLOCKS, THREADS>>>(dens, cols, tsil, timg,
                                            focal, princ, Rm, Tv, out);
}

// round 5
// speedup vs baseline: 1.5298x; 1.5298x over previous
#include <cuda_runtime.h>
#include <math.h>

// ---------------- problem constants ----------------
#define N_CAM   2
#define PH      96
#define PW      144
#define NPTS    200
#define MIN_D   1.0f
#define MAX_D   4000.0f
#define VD      32
#define VH      128
#define VW      384
#define VOXELSZ 2.5f

#define DHW   (VD*VH*VW)
#define HW    (VH*VW)
#define NRAYS (N_CAM*PH*PW)
#define STEP_D ((MAX_D - MIN_D) / (float)(NPTS - 1))

#define HX (VOXELSZ * (VW - 1) * 0.5f)
#define HY (VOXELSZ * (VH - 1) * 0.5f)
#define HZ (VOXELSZ * (VD - 1) * 0.5f)

#define LPR 4                                    // lanes per ray
#define THREADS    256
#define RAY_BLOCKS ((NRAYS * LPR) / THREADS)     // 432 (exact)
#define BEV_BLOCKS ((HW / 4 + THREADS - 1) / THREADS)  // 48
#define NBLOCKS    (RAY_BLOCKS + BEV_BLOCKS)     // 480

// scratch for deterministic cross-block reduction (overwritten every replay)
__device__ float    g_partial[NBLOCKS][3];
__device__ unsigned g_count = 0;

__device__ __forceinline__ float huber01(float x, float y) {
    float d = x - y;
    float v = fmaf(d * d, 100.0f, 1.0f);
    return (sqrtf(v) - 1.0f) * 0.1f;
}

__global__ void __launch_bounds__(THREADS)
fused_loss_kernel(
    const float* __restrict__ dens,   // (VD,VH,VW)
    const float* __restrict__ cols,   // (3,VD,VH,VW)
    const float* __restrict__ tsil,   // (N_CAM,PH,PW)
    const float* __restrict__ timg,   // (N_CAM,PH,PW,3)
    const float* __restrict__ focal,
    const float* __restrict__ princ,
    const float* __restrict__ Rm,
    const float* __restrict__ Tv,
    float* __restrict__ out)
{
    __shared__ float s_a[THREADS/32], s_b[THREADS/32];
    __shared__ bool  s_last;

    const int tid  = threadIdx.x;
    const int lane = tid & 31;
    const int warp = tid >> 5;

    float p0 = 0.0f, p1 = 0.0f, p2 = 0.0f;   // block partials (color, sil, bev)

    if (blockIdx.x < RAY_BLOCKS) {
        // ---------------- ray blocks: LPR lanes per ray ----------------
        int g   = blockIdx.x * THREADS + tid;    // < NRAYS*LPR exactly
        int idx = g >> 2;                         // ray id
        int sub = g & 3;                          // lane-within-ray

        int w = idx % PW;
        int h = (idx / PW) % PH;
        int n = idx / (PW * PH);

        float fx = focal[n*2+0], fy = focal[n*2+1];
        float px = princ[n*2+0], py = princ[n*2+1];
        float dcx = ((float)w + 0.5f - px) / fx;
        float dcy = ((float)h + 0.5f - py) / fy;

        const float* R = Rm + n*9;
        float Tx = Tv[n*3+0], Ty = Tv[n*3+1], Tz = Tv[n*3+2];

        float dx = dcx*R[0] + dcy*R[1] + R[2];
        float dy = dcx*R[3] + dcy*R[4] + R[5];
        float dz = dcx*R[6] + dcy*R[7] + R[8];
        float ox = -(Tx*R[0] + Ty*R[1] + Tz*R[2]);
        float oy = -(Tx*R[3] + Ty*R[4] + Tz*R[5]);
        float oz = -(Tx*R[6] + Ty*R[7] + Tz*R[8]);

        // grid-space linear form: g_axis(t) = A + B*t (used for BOTH the slab
        // test and per-sample coordinates)
        const float cx = 0.5f * (VW - 1), cy = 0.5f * (VH - 1), cz = 0.5f * (VD - 1);
        float Ax = ox / HX * cx + cx, Bx = dx / HX * cx;
        float Ay = oy / HY * cy + cy, By = dy / HY * cy;
        float Az = oz / HZ * cz + cz, Bz = dz / HZ * cz;

        float tmin = MIN_D, tmax = MAX_D;
        {
            const float lo = -1.001f, hi = (float)VW + 0.001f;
            if (fabsf(Bx) > 1e-20f) {
                float rB = __fdividef(1.0f, Bx);
                float t1 = (lo - Ax) * rB, t2 = (hi - Ax) * rB;
                tmin = fmaxf(tmin, fminf(t1, t2)); tmax = fminf(tmax, fmaxf(t1, t2));
            } else if (Ax <= lo || Ax >= hi) { tmax = tmin - 1.0f; }
        }
        {
            const float lo = -1.001f, hi = (float)VH + 0.001f;
            if (fabsf(By) > 1e-20f) {
                float rB = __fdividef(1.0f, By);
                float t1 = (lo - Ay) * rB, t2 = (hi - Ay) * rB;
                tmin = fmaxf(tmin, fminf(t1, t2)); tmax = fminf(tmax, fmaxf(t1, t2));
            } else if (Ay <= lo || Ay >= hi) { tmax = tmin - 1.0f; }
        }
        {
            const float lo = -1.001f, hi = (float)VD + 0.001f;
            if (fabsf(Bz) > 1e-20f) {
                float rB = __fdividef(1.0f, Bz);
                float t1 = (lo - Az) * rB, t2 = (hi - Az) * rB;
                tmin = fmaxf(tmin, fminf(t1, t2)); tmax = fminf(tmax, fmaxf(t1, t2));
            } else if (Az <= lo || Az >= hi) { tmax = tmin - 1.0f; }
        }

        int i0 = 0, i1 = -1;
        if (tmax >= tmin) {
            i0 = (int)ceilf ((tmin - MIN_D) / STEP_D - 1e-4f);
            i1 = (int)floorf((tmax - MIN_D) / STEP_D + 1e-4f);
            if (i0 < 0) i0 = 0;
            if (i1 > NPTS - 1) i1 = NPTS - 1;
        }

        // this lane's contiguous chunk of samples
        int nsamp = i1 - i0 + 1;                 // may be <= 0
        int chunk = (nsamp + LPR - 1) >> 2;      // per-lane count (>=0)
        int s0 = i0 + sub * chunk;
        int s1 = s0 + chunk - 1;
        if (s1 > i1) s1 = i1;

        float trans = 1.0f;                      // local prod(1-d)
        float fr = 0.0f, fg = 0.0f, fb = 0.0f;   // local over-composited rgb

        for (int i = s0; i <= s1; ++i) {
            float t  = fmaf((float)i, STEP_D, MIN_D);
            float gx = fmaf(t, Bx, Ax);
            float gy = fmaf(t, By, Ay);
            float gz = fmaf(t, Bz, Az);

            float x0f = floorf(gx), y0f = floorf(gy), z0f = floorf(gz);
            float frx = gx - x0f, fry = gy - y0f, frz = gz - z0f;
            int ix0 = (int)x0f, iy0 = (int)y0f, iz0 = (int)z0f;

            // validity folded into per-axis weights; indices clamped (branch-free)
            float wx0 = (ix0     >= 0 && ix0     < VW) ? 1.0f - frx : 0.0f;
            float wx1 = (ix0 + 1 >= 0 && ix0 + 1 < VW) ? frx        : 0.0f;
            float wy0 = (iy0     >= 0 && iy0     < VH) ? 1.0f - fry : 0.0f;
            float wy1 = (iy0 + 1 >= 0 && iy0 + 1 < VH) ? fry        : 0.0f;
            float wz0 = (iz0     >= 0 && iz0     < VD) ? 1.0f - frz : 0.0f;
            float wz1 = (iz0 + 1 >= 0 && iz0 + 1 < VD) ? frz        : 0.0f;

            int x0 = min(max(ix0,     0), VW - 1);
            int x1 = min(max(ix0 + 1, 0), VW - 1);
            int y0 = min(max(iy0,     0), VH - 1) * VW;
            int y1 = min(max(iy0 + 1, 0), VH - 1) * VW;
            int z0 = min(max(iz0,     0), VD - 1) * HW;
            int z1 = min(max(iz0 + 1, 0), VD - 1) * HW;

            int f000 = z0 + y0 + x0, f001 = z0 + y0 + x1;
            int f010 = z0 + y1 + x0, f011 = z0 + y1 + x1;
            int f100 = z1 + y0 + x0, f101 = z1 + y0 + x1;
            int f110 = z1 + y1 + x0, f111 = z1 + y1 + x1;

            float w000 = wz0*wy0*wx0, w001 = wz0*wy0*wx1;
            float w010 = wz0*wy1*wx0, w011 = wz0*wy1*wx1;
            float w100 = wz1*wy0*wx0, w101 = wz1*wy0*wx1;
            float w110 = wz1*wy1*wx0, w111 = wz1*wy1*wx1;

            // issue all loads up front (max MLP)
            float d000 = __ldg(dens + f000), d001 = __ldg(dens + f001);
            float d010 = __ldg(dens + f010), d011 = __ldg(dens + f011);
            float d100 = __ldg(dens + f100), d101 = __ldg(dens + f101);
            float d110 = __ldg(dens + f110), d111 = __ldg(dens + f111);

            const float* cr = cols;
            const float* cg = cols + DHW;
            const float* cb = cols + 2*DHW;
            float r000 = __ldg(cr + f000), r001 = __ldg(cr + f001);
            float r010 = __ldg(cr + f010), r011 = __ldg(cr + f011);
            float r100 = __ldg(cr + f100), r101 = __ldg(cr + f101);
            float r110 = __ldg(cr + f110), r111 = __ldg(cr + f111);
            float g000 = __ldg(cg + f000), g001 = __ldg(cg + f001);
            float g010 = __ldg(cg + f010), g011 = __ldg(cg + f011);
            float g100 = __ldg(cg + f100), g101 = __ldg(cg + f101);
            float g110 = __ldg(cg + f110), g111 = __ldg(cg + f111);
            float b000 = __ldg(cb + f000), b001 = __ldg(cb + f001);
            float b010 = __ldg(cb + f010), b011 = __ldg(cb + f011);
            float b100 = __ldg(cb + f100), b101 = __ldg(cb + f101);
            float b110 = __ldg(cb + f110), b111 = __ldg(cb + f111);

            float ad = w000*d000 + w001*d001 + w010*d010 + w011*d011
                     + w100*d100 + w101*d101 + w110*d110 + w111*d111;
            float ar = w000*r000 + w001*r001 + w010*r010 + w011*r011
                     + w100*r100 + w101*r101 + w110*r110 + w111*r111;
            float ag = w000*g000 + w001*g001 + w010*g010 + w011*g011
                     + w100*g100 + w101*g101 + w110*g110 + w111*g111;
            float ab = w000*b000 + w001*b001 + w010*b010 + w011*b011
                     + w100*b100 + w101*b101 + w110*b110 + w111*b111;

            float wgt = ad * trans;
            fr = fmaf(wgt, ar, fr);
            fg = fmaf(wgt, ag, fg);
            fb = fmaf(wgt, ab, fb);
            trans *= (1.0f - ad);
        }

        // ---- compose the 4 lane-chunks: (F,T) ⊗ (F',T') = (F + T F', T T') ----
        #pragma unroll
        for (int o = 1; o < LPR; o <<= 1) {
            float Tn  = __shfl_down_sync(0xffffffffu, trans, o, LPR);
            float frn = __shfl_down_sync(0xffffffffu, fr,    o, LPR);
            float fgn = __shfl_down_sync(0xffffffffu, fg,    o, LPR);
            float fbn = __shfl_down_sync(0xffffffffu, fb,    o, LPR);
            fr = fmaf(trans, frn, fr);
            fg = fmaf(trans, fgn, fg);
            fb = fmaf(trans, fbn, fb);
            trans *= Tn;
        }

        float csum = 0.0f, ssum = 0.0f;
        if (sub == 0) {
            float opacity = 1.0f - trans;
            ssum = huber01(opacity, tsil[idx]);
            const float* ti = timg + (size_t)idx * 3;
            csum = huber01(fr, ti[0]) + huber01(fg, ti[1]) + huber01(fb, ti[2]);
        }

        // block reduce
        #pragma unroll
        for (int o = 16; o > 0; o >>= 1) {
            csum += __shfl_down_sync(0xffffffffu, csum, o);
            ssum += __shfl_down_sync(0xffffffffu, ssum, o);
        }
        if (lane == 0) { s_a[warp] = csum; s_b[warp] = ssum; }
        __syncthreads();
        if (warp == 0) {
            float a = (lane < THREADS/32) ? s_a[lane] : 0.0f;
            float b = (lane < THREADS/32) ? s_b[lane] : 0.0f;
            #pragma unroll
            for (int o = 4; o > 0; o >>= 1) {
                a += __shfl_down_sync(0xffffffffu, a, o);
                b += __shfl_down_sync(0xffffffffu, b, o);
            }
            if (lane == 0) { p0 = a; p1 = b; }
        }
    } else {
        // ---------------- BEV blocks: mean |max_z dens| ----------------
        int cidx = (blockIdx.x - RAY_BLOCKS) * THREADS + tid;   // float4 column index
        float bsum = 0.0f;
        if (cidx < HW / 4) {
            const float4* d4 = (const float4*)dens;
            float4 m = __ldg(d4 + cidx);
            #pragma unroll
            for (int z = 1; z < VD; ++z) {
                float4 v = __ldg(d4 + cidx + z * (HW / 4));
                m.x = fmaxf(m.x, v.x); m.y = fmaxf(m.y, v.y);
                m.z = fmaxf(m.z, v.z); m.w = fmaxf(m.w, v.w);
            }
            bsum = fabsf(m.x) + fabsf(m.y) + fabsf(m.z) + fabsf(m.w);
        }
        #pragma unroll
        for (int o = 16; o > 0; o >>= 1)
            bsum += __shfl_down_sync(0xffffffffu, bsum, o);
        if (lane == 0) s_a[warp] = bsum;
        __syncthreads();
        if (warp == 0) {
            float a = (lane < THREADS/32) ? s_a[lane] : 0.0f;
            #pragma unroll
            for (int o = 4; o > 0; o >>= 1)
                a += __shfl_down_sync(0xffffffffu, a, o);
            if (lane == 0) p2 = a;
        }
    }

    // ---------------- publish partial, last block reduces ----------------
    if (tid == 0) {
        g_partial[blockIdx.x][0] = p0;
        g_partial[blockIdx.x][1] = p1;
        g_partial[blockIdx.x][2] = p2;
        __threadfence();
        unsigned prev = atomicAdd(&g_count, 1u);
        s_last = (prev == NBLOCKS - 1);
    }
    __syncthreads();

    if (s_last) {
        float a = 0.0f, b = 0.0f, c = 0.0f;
        for (int i = tid; i < NBLOCKS; i += THREADS) {
            a += g_partial[i][0];
            b += g_partial[i][1];
            c += g_partial[i][2];
        }
        #pragma unroll
        for (int o = 16; o > 0; o >>= 1) {
            a += __shfl_down_sync(0xffffffffu, a, o);
            b += __shfl_down_sync(0xffffffffu, b, o);
            c += __shfl_down_sync(0xffffffffu, c, o);
        }
        __shared__ float r_a[THREADS/32], r_b[THREADS/32], r_c[THREADS/32];
        if (lane == 0) { r_a[warp] = a; r_b[warp] = b; r_c[warp] = c; }
        __syncthreads();
        if (warp == 0) {
            a = (lane < THREADS/32) ? r_a[lane] : 0.0f;
            b = (lane < THREADS/32) ? r_b[lane] : 0.0f;
            c = (lane < THREADS/32) ? r_c[lane] : 0.0f;
            #pragma unroll
            for (int o = 4; o > 0; o >>= 1) {
                a += __shfl_down_sync(0xffffffffu, a, o);
                b += __shfl_down_sync(0xffffffffu, b, o);
                c += __shfl_down_sync(0xffffffffu, c, o);
            }
            if (lane == 0) {
                out[0] = a * (1.0f / (float)(NRAYS * 3));
                out[1] = b * (1.0f / (float)NRAYS);
                out[2] = c * (1.0f / (float)HW);
                g_count = 0;   // reset for next graph replay
            }
        }
    }
}

extern "C" void kernel_launch(void* const* d_in, const int* in_sizes, int n_in,
                              void* d_out, int out_size) {
    const float* dens  = (const float*)d_in[0];
    const float* cols  = (const float*)d_in[1];
    const float* tsil  = (const float*)d_in[2];
    const float* timg  = (const float*)d_in[3];
    const float* focal = (const float*)d_in[4];
    const float* princ = (const float*)d_in[5];
    const float* Rm    = (const float*)d_in[6];
    const float* Tv    = (const float*)d_in[7];
    float* out = (float*)d_out;

    fused_loss_kernel<<<NBLOCKS, THREADS>>>(dens, cols, tsil, timg,
                                            focal, princ, Rm, Tv, out);
}